// round 6
// baseline (speedup 1.0000x reference)
#include <cuda_runtime.h>
#include <math.h>

#define NN 4000
#define NE 60000
#define MAXE 192          // per-node smem softmax cache; global fallback beyond

// ---------------- scratch ----------------
__device__ float g_WA[2][4096];   // Ws@Wa per set
__device__ float g_WTA[2][4096];  // Wt@Wa per set
__device__ float g_WeA[2][2048];  // We@Wa per set
__device__ float g_Ut[2][512];    // [set][hd][h]
__device__ float g_G[2][256];     // [set][hd][ce] = Ut@We^T
__device__ float g_At[NN * 1024]; // per-node X@WtA_own  [n][m][64]
__device__ float g_Y3[NN * 576];  // [n][part][3][64]; part 0=Ys set0,1=Ys set1,2=Yt own
__device__ float g_as[NE * 64];   // per-edge src partial of alpha features
__device__ float g_eexp[NE * 8];  // overflow fallback only
__device__ int   g_mask[NN];
__device__ int   g_scnt[NN + 8], g_dcnt[NN + 8];
__device__ int   g_sofs[NN + 8], g_dofs[NN + 8];
__device__ int   g_scur[NN + 8], g_dcur[NN + 8];
__device__ int   g_slist[NE], g_dlist[NE];

struct ParSet {
    const float *emb_s, *emb_t, *w_d, *We, *Ws, *Wt, *Wa, *va, *Wv, *Wo;
};
struct Par2 { ParSet s[2]; };

// ---------------- mask dtype sniff + zero CSR counts ----------------
__global__ void k_mask(const void* nm) {
    __shared__ int s_max, s_s1;
    if (threadIdx.x == 0) { s_max = 0; s_s1 = 0; }
    __syncthreads();
    const unsigned char* bp = (const unsigned char*)nm;
    int lm = 0, ls = 0;
    for (int i = threadIdx.x; i < NN; i += blockDim.x) {
        int v = bp[i];
        if (v > lm) lm = v;
        if ((i & 3) == 1) ls += v;
    }
    atomicMax(&s_max, lm);
    atomicAdd(&s_s1, ls);
    __syncthreads();
    int mode = (s_max > 1) ? 2 : (s_s1 > 0 ? 0 : 1);
    for (int n = threadIdx.x; n < NN; n += blockDim.x) {
        int v;
        if (mode == 0)      v = (bp[n] != 0);
        else if (mode == 1) v = (((const int*)nm)[n] != 0);
        else                v = (((const float*)nm)[n] != 0.0f);
        g_mask[n] = v;
    }
    for (int n = threadIdx.x; n < NN + 8; n += blockDim.x) {
        g_scnt[n] = 0; g_dcnt[n] = 0;
    }
}

// ---------------- CSR: histogram ----------------
__global__ void k_hist(const int* __restrict__ ei) {
    int e = blockIdx.x * blockDim.x + threadIdx.x;
    if (e < NE) {
        atomicAdd(&g_scnt[ei[e]], 1);
        atomicAdd(&g_dcnt[ei[NE + e]], 1);
    }
}

// ---------------- CSR: exclusive scan (1 block, 1024 thr, 4 elems/thr) ----------------
__global__ void k_scan() {
    __shared__ int ws[32], wd[32];
    int tid = threadIdx.x, lane = tid & 31, wid = tid >> 5;
    // ---- src ----
    {
        int base = tid * 4, c[4], tot = 0;
        #pragma unroll
        for (int k = 0; k < 4; k++) { c[k] = (base + k < NN) ? g_scnt[base + k] : 0; tot += c[k]; }
        int v = tot;
        #pragma unroll
        for (int off = 1; off < 32; off <<= 1) {
            int t = __shfl_up_sync(0xffffffffu, v, off);
            if (lane >= off) v += t;
        }
        if (lane == 31) ws[wid] = v;
        __syncthreads();
        if (wid == 0) {
            int w = ws[lane];
            #pragma unroll
            for (int off = 1; off < 32; off <<= 1) {
                int t = __shfl_up_sync(0xffffffffu, w, off);
                if (lane >= off) w += t;
            }
            ws[lane] = w;
        }
        __syncthreads();
        int run = (v - tot) + (wid > 0 ? ws[wid - 1] : 0);
        #pragma unroll
        for (int k = 0; k < 4; k++) {
            int idx = base + k;
            if (idx <= NN) { g_sofs[idx] = run; g_scur[idx] = run; }
            run += c[k];
        }
    }
    __syncthreads();
    // ---- dst ----
    {
        int base = tid * 4, c[4], tot = 0;
        #pragma unroll
        for (int k = 0; k < 4; k++) { c[k] = (base + k < NN) ? g_dcnt[base + k] : 0; tot += c[k]; }
        int v = tot;
        #pragma unroll
        for (int off = 1; off < 32; off <<= 1) {
            int t = __shfl_up_sync(0xffffffffu, v, off);
            if (lane >= off) v += t;
        }
        if (lane == 31) wd[wid] = v;
        __syncthreads();
        if (wid == 0) {
            int w = wd[lane];
            #pragma unroll
            for (int off = 1; off < 32; off <<= 1) {
                int t = __shfl_up_sync(0xffffffffu, w, off);
                if (lane >= off) w += t;
            }
            wd[lane] = w;
        }
        __syncthreads();
        int run = (v - tot) + (wid > 0 ? wd[wid - 1] : 0);
        #pragma unroll
        for (int k = 0; k < 4; k++) {
            int idx = base + k;
            if (idx <= NN) { g_dofs[idx] = run; g_dcur[idx] = run; }
            run += c[k];
        }
    }
}

// ---------------- CSR: scatter ----------------
__global__ void k_scatter(const int* __restrict__ ei) {
    int e = blockIdx.x * blockDim.x + threadIdx.x;
    if (e < NE) {
        int p1 = atomicAdd(&g_scur[ei[e]], 1);
        g_slist[p1] = e;
        int p2 = atomicAdd(&g_dcur[ei[NE + e]], 1);
        g_dlist[p2] = e;
    }
}

// ---------------- weight folds ----------------
__global__ void k_small(Par2 P) {
    int tid = blockIdx.x * blockDim.x + threadIdx.x;
    int stride = gridDim.x * blockDim.x;
    for (int i = tid; i < 16384; i += stride) {
        int mat = i >> 12, c = (i >> 6) & 63, j = i & 63;
        int set = mat & 1;
        const float* W  = (mat < 2) ? P.s[set].Ws : P.s[set].Wt;
        const float* Wa = P.s[set].Wa;
        float s = 0.0f;
        for (int h = 0; h < 64; h++) s += W[c * 64 + h] * Wa[h * 64 + j];
        if (mat < 2) g_WA[set][c * 64 + j] = s;
        else         g_WTA[set][c * 64 + j] = s;
    }
    for (int i = tid; i < 4096; i += stride) {
        int set = i >> 11, ce = (i >> 6) & 31, j = i & 63;
        const float* We = P.s[set].We;
        const float* Wa = P.s[set].Wa;
        float s = 0.0f;
        for (int h = 0; h < 64; h++) s += We[ce * 64 + h] * Wa[h * 64 + j];
        g_WeA[set][ce * 64 + j] = s;
    }
    for (int i = tid; i < 1024; i += stride) {
        int set = i >> 9, r = i & 511, hd = r >> 6, h = r & 63;
        const float* Wv = P.s[set].Wv;
        const float* Wo = P.s[set].Wo;
        float s = 0.0f;
        #pragma unroll
        for (int vc = 0; vc < 8; vc++)
            s += Wv[h * 64 + hd * 8 + vc] * Wo[hd * 8 + vc];
        g_Ut[set][hd * 64 + h] = s;
    }
    // G[set][hd][ce] = sum_h Ut[hd][h] * We[ce][h]
    for (int i = tid; i < 512; i += stride) {
        int set = i >> 8, r = i & 255, hd = r >> 5, ce = r & 31;
        const float* Wv = P.s[set].Wv;
        const float* Wo = P.s[set].Wo;
        const float* We = P.s[set].We;
        float s = 0.0f;
        for (int h = 0; h < 64; h++) {
            float ut = 0.0f;
            #pragma unroll
            for (int vc = 0; vc < 8; vc++)
                ut += Wv[h * 64 + vc] * Wo[hd * 8 + vc] * 0.0f + Wv[h * 64 + hd * 8 + vc] * Wo[hd * 8 + vc];
            s += ut * We[ce * 64 + h];
        }
        g_G[set][hd * 32 + ce] = s;
    }
}

// ---------------- per-node: At = X@WtA_own, Y3 rows 1..3 ----------------
__global__ __launch_bounds__(256)
void k_node(const float* __restrict__ x, Par2 P) {
    __shared__ float Xs[64 * 20];          // [c][m] padded
    int n = blockIdx.x;
    int tid = threadIdx.x;
    int bn = g_mask[n];

    for (int i = tid; i < 1024; i += 256) {
        int m = i >> 6, c = i & 63;
        Xs[c * 20 + m] = x[(size_t)n * 1024 + i];
    }
    __syncthreads();

    // At: thread (m, j4)
    {
        int m = tid >> 4;
        int j4 = (tid & 15) * 4;
        const float* W = g_WTA[bn];
        float4 acc = {0, 0, 0, 0};
        #pragma unroll 8
        for (int c = 0; c < 64; c++) {
            float xv = Xs[c * 20 + m];
            float4 w = __ldg((const float4*)(W + c * 64 + j4));
            acc.x += xv * w.x; acc.y += xv * w.y; acc.z += xv * w.z; acc.w += xv * w.w;
        }
        *(float4*)(g_At + (size_t)n * 1024 + m * 64 + j4) = acc;
    }
    // Y3: 144 threads, (mat, r, j4)
    if (tid < 144) {
        int mat = tid / 48;
        int rr  = (tid / 16) % 3;
        int j4  = (tid & 15) * 4;
        const float* W = (mat == 0) ? P.s[0].Ws : (mat == 1) ? P.s[1].Ws : P.s[bn].Wt;
        float4 acc = {0, 0, 0, 0};
        #pragma unroll 8
        for (int c = 0; c < 64; c++) {
            float xv = Xs[c * 20 + 1 + rr];
            float4 w = __ldg((const float4*)(W + c * 64 + j4));
            acc.x += xv * w.x; acc.y += xv * w.y; acc.z += xv * w.z; acc.w += xv * w.w;
        }
        *(float4*)(g_Y3 + (size_t)n * 576 + mat * 192 + rr * 64 + j4) = acc;
    }
}

// ---------------- P1a: src-major per-edge alpha-feature partial ----------------
__global__ __launch_bounds__(256)
void k_p1a(const float* __restrict__ x, const int* __restrict__ ei,
           const float* __restrict__ wig) {
    __shared__ float sWA[2 * 4096];    // 32KB
    __shared__ float sX[1024];         // 4KB, [m][c] row-major
    __shared__ float sxs[16][68];      // per-half-warp xs0 scratch (padded)
    int tid = threadIdx.x;
    int hw  = tid >> 4;                // 0..15
    int q   = tid & 15;
    unsigned hm = 0xFFFFu << (threadIdx.x & 16);   // half-warp mask (convergent lanes)

    for (int i = tid * 4; i < 8192; i += 1024)
        *(float4*)(sWA + i) = __ldg((const float4*)(&g_WA[0][0] + i));
    __syncthreads();

    for (int n = blockIdx.x; n < NN; n += gridDim.x) {
        __syncthreads();
        for (int i = tid; i < 1024; i += 256) sX[i] = __ldg(x + (size_t)n * 1024 + i);
        __syncthreads();
        int e0 = g_sofs[n], e1 = g_sofs[n + 1];
        for (int i = e0 + hw; i < e1; i += 16) {
            int e = g_slist[i];
            int dst = ei[NE + e];
            int b = g_mask[dst];
            // xs0[4q..4q+3] = sum_m D0[m] * X[m][4q..]
            float dq = __ldg(wig + (size_t)e * 256 + q);
            float4 xs = {0, 0, 0, 0};
            #pragma unroll
            for (int m = 0; m < 16; m++) {
                float dm = __shfl_sync(hm, dq, m, 16);
                float4 xv = *(const float4*)(sX + m * 64 + q * 4);
                xs.x += dm * xv.x; xs.y += dm * xv.y; xs.z += dm * xv.z; xs.w += dm * xv.w;
            }
            *(float4*)(&sxs[hw][q * 4]) = xs;
            __syncwarp(hm);
            // a[4q..] = xs0 @ WsA_b
            const float* W = sWA + b * 4096;
            float4 a = {0, 0, 0, 0};
            #pragma unroll 8
            for (int c = 0; c < 64; c++) {
                float xc = sxs[hw][c];
                float4 w = *(const float4*)(W + c * 64 + q * 4);
                a.x += xc * w.x; a.y += xc * w.y; a.z += xc * w.z; a.w += xc * w.w;
            }
            *(float4*)(g_as + (size_t)e * 64 + q * 4) = a;
            __syncwarp(hm);
        }
    }
}

// ---------------- P1b: dst-major fused logits+softmax+values+output ----------------
__global__ __launch_bounds__(256)
void k_p1b(const int* __restrict__ zn, const float* __restrict__ dist,
           const int* __restrict__ ei, const float* __restrict__ wig,
           Par2 P, float* __restrict__ out) {
    __shared__ float sWeA[2 * 2048];   // 16KB
    __shared__ float sUt[2 * 512];     // 4KB
    __shared__ float sG[2 * 256];      // 2KB
    __shared__ float sva[2 * 64];
    __shared__ float swd[2 * 32];
    __shared__ float sAt[1024];        // 4KB
    __shared__ float sYt[192];
    __shared__ float sembt[32];
    __shared__ float sexp[MAXE * 8];   // 6KB
    __shared__ float sesum[8];
    __shared__ float sout[3];
    int tid = threadIdx.x;
    int hw  = tid >> 4;
    int q   = tid & 15;
    unsigned hm = 0xFFFFu << (threadIdx.x & 16);   // half-warp mask

    for (int i = tid * 4; i < 4096; i += 1024)
        *(float4*)(sWeA + i) = __ldg((const float4*)(&g_WeA[0][0] + i));
    for (int i = tid * 4; i < 1024; i += 1024)
        *(float4*)(sUt + i) = __ldg((const float4*)(&g_Ut[0][0] + i));
    for (int i = tid; i < 512; i += 256)                 // FIX: full 512 floats
        sG[i] = (&g_G[0][0])[i];
    if (tid < 64)  sva[tid] = __ldg(P.s[0].va + tid);
    if (tid >= 64 && tid < 128) sva[tid] = __ldg(P.s[1].va + tid - 64);
    if (tid >= 128 && tid < 160) swd[tid - 128] = __ldg(P.s[0].w_d + tid - 128);
    if (tid >= 160 && tid < 192) swd[32 + tid - 160] = __ldg(P.s[1].w_d + tid - 160);
    __syncthreads();

    for (int n = blockIdx.x; n < NN; n += gridDim.x) {
        __syncthreads();
        int b = g_mask[n];
        int zt = zn[n];
        for (int i = tid; i < 1024; i += 256) sAt[i] = g_At[(size_t)n * 1024 + i];
        for (int i = tid; i < 192; i += 256) sYt[i] = g_Y3[(size_t)n * 576 + 384 + i];
        if (tid < 32) sembt[tid] = __ldg(P.s[b].emb_t + zt * 32 + tid);
        if (tid < 8)  sesum[tid] = 0.0f;
        if (tid >= 8 && tid < 11) sout[tid - 8] = 0.0f;
        __syncthreads();

        int e0 = g_dofs[n], e1 = g_dofs[n + 1];
        const float* embS = P.s[b].emb_s;

        // ---- sweep 1: logits ----
        for (int i = e0 + hw; i < e1; i += 16) {
            int e = g_dlist[i];
            int src = ei[e];
            int zs = zn[src];
            float dd = __ldg(dist + e);
            float z0 = dd * swd[b * 32 + q]      + __ldg(embS + zs * 32 + q)      + sembt[q];
            float z1 = dd * swd[b * 32 + q + 16] + __ldg(embS + zs * 32 + q + 16) + sembt[q + 16];
            float ev0 = z0 / (1.0f + __expf(-z0));
            float ev1 = z1 / (1.0f + __expf(-z1));
            float4 a = __ldg((const float4*)(g_as + (size_t)e * 64) + q);
            float dq = __ldg(wig + (size_t)e * 256 + q);
            #pragma unroll
            for (int m = 0; m < 16; m++) {
                float dm = __shfl_sync(hm, dq, m, 16);
                float4 t = *(const float4*)(sAt + m * 64 + q * 4);
                a.x += dm * t.x; a.y += dm * t.y; a.z += dm * t.z; a.w += dm * t.w;
            }
            #pragma unroll 8
            for (int ce = 0; ce < 32; ce++) {
                float evv = __shfl_sync(hm, (ce < 16) ? ev0 : ev1, ce & 15, 16);
                float4 w = *(const float4*)(sWeA + b * 2048 + ce * 64 + q * 4);
                a.x += evv * w.x; a.y += evv * w.y; a.z += evv * w.z; a.w += evv * w.w;
            }
            float4 vv = *(const float4*)(sva + b * 64 + q * 4);
            float s = ((a.x > 0.f) ? a.x : 0.2f * a.x) * vv.x
                    + ((a.y > 0.f) ? a.y : 0.2f * a.y) * vv.y
                    + ((a.z > 0.f) ? a.z : 0.2f * a.z) * vv.z
                    + ((a.w > 0.f) ? a.w : 0.2f * a.w) * vv.w;
            s += __shfl_xor_sync(hm, s, 1, 16);
            if ((q & 1) == 0) {
                int hd = q >> 1;
                float el = __expf(s);
                int idx = i - e0;
                if (idx < MAXE) sexp[idx * 8 + hd] = el;
                else            g_eexp[(size_t)e * 8 + hd] = el;
                atomicAdd(&sesum[hd], el);
            }
        }
        __syncthreads();

        // ---- sweep 2: alpha -> output ----
        for (int i = e0 + hw; i < e1; i += 16) {
            int e = g_dlist[i];
            int src = ei[e];
            int zs = zn[src];
            int idx = i - e0;
            float al = 0.0f;
            if (q < 8) {
                float el = (idx < MAXE) ? sexp[idx * 8 + q] : g_eexp[(size_t)e * 8 + q];
                al = el / (sesum[q] + 1e-9f);
            }
            float4 p = {0, 0, 0, 0};
            #pragma unroll
            for (int hd = 0; hd < 8; hd++) {
                float av = __shfl_sync(hm, al, hd, 16);
                float4 u = *(const float4*)(sUt + b * 512 + hd * 64 + q * 4);
                p.x += av * u.x; p.y += av * u.y; p.z += av * u.z; p.w += av * u.w;
            }
            float dd = __ldg(dist + e);
            float z0 = dd * swd[b * 32 + q]      + __ldg(embS + zs * 32 + q)      + sembt[q];
            float z1 = dd * swd[b * 32 + q + 16] + __ldg(embS + zs * 32 + q + 16) + sembt[q + 16];
            float ev0 = z0 / (1.0f + __expf(-z0));
            float ev1 = z1 / (1.0f + __expf(-z1));
            // pinj via G
            float w0 = 0.0f, w1 = 0.0f;
            #pragma unroll
            for (int hd = 0; hd < 8; hd++) {
                float av = __shfl_sync(hm, al, hd, 16);
                w0 += av * sG[b * 256 + hd * 32 + q];
                w1 += av * sG[b * 256 + hd * 32 + q + 16];
            }
            float pinj = ev0 * w0 + ev1 * w1;
            // output dots
            const float4* Ys = (const float4*)(g_Y3 + (size_t)src * 576 + b * 192);
            float o0, o1, o2;
            {
                float4 y, t;
                y = __ldg(Ys + q);       t = *(const float4*)(sYt + q * 4);
                o0 = p.x*(y.x+t.x) + p.y*(y.y+t.y) + p.z*(y.z+t.z) + p.w*(y.w+t.w);
                y = __ldg(Ys + 16 + q);  t = *(const float4*)(sYt + 64 + q * 4);
                o1 = p.x*(y.x+t.x) + p.y*(y.y+t.y) + p.z*(y.z+t.z) + p.w*(y.w+t.w);
                y = __ldg(Ys + 32 + q);  t = *(const float4*)(sYt + 128 + q * 4);
                o2 = p.x*(y.x+t.x) + p.y*(y.y+t.y) + p.z*(y.z+t.z) + p.w*(y.w+t.w);
            }
            #pragma unroll
            for (int off = 8; off; off >>= 1) {
                o0   += __shfl_down_sync(hm, o0, off, 16);
                o1   += __shfl_down_sync(hm, o1, off, 16);
                o2   += __shfl_down_sync(hm, o2, off, 16);
                pinj += __shfl_down_sync(hm, pinj, off, 16);
            }
            if (q == 0) {
                float d1 = __ldg(wig + (size_t)e * 256 + 1);
                float d2 = __ldg(wig + (size_t)e * 256 + 2);
                float d3 = __ldg(wig + (size_t)e * 256 + 3);
                atomicAdd(&sout[0], o0 + pinj * d1);
                atomicAdd(&sout[1], o1 + pinj * d2);
                atomicAdd(&sout[2], o2 + pinj * d3);
            }
        }
        __syncthreads();
        if (tid < 3) out[n * 3 + tid] = sout[tid];
    }
}

extern "C" void kernel_launch(void* const* d_in, const int* in_sizes, int n_in,
                              void* d_out, int out_size) {
    const float* x    = (const float*)d_in[0];
    const int*   zn   = (const int*)d_in[1];
    const float* dist = (const float*)d_in[2];
    const int*   ei   = (const int*)d_in[3];
    const void*  nm   = d_in[4];
    const float* wig  = (const float*)d_in[5];

    Par2 P;
    for (int s = 0; s < 2; s++) {
        int base = 6 + s * 10;
        P.s[s].emb_s = (const float*)d_in[base + 0];
        P.s[s].emb_t = (const float*)d_in[base + 1];
        P.s[s].w_d   = (const float*)d_in[base + 2];
        P.s[s].We    = (const float*)d_in[base + 3];
        P.s[s].Ws    = (const float*)d_in[base + 4];
        P.s[s].Wt    = (const float*)d_in[base + 5];
        P.s[s].Wa    = (const float*)d_in[base + 6];
        P.s[s].va    = (const float*)d_in[base + 7];
        P.s[s].Wv    = (const float*)d_in[base + 8];
        P.s[s].Wo    = (const float*)d_in[base + 9];
    }
    float* out = (float*)d_out;

    k_mask<<<1, 1024>>>(nm);
    k_hist<<<(NE + 255) / 256, 256>>>(ei);
    k_scan<<<1, 1024>>>();
    k_scatter<<<(NE + 255) / 256, 256>>>(ei);
    k_small<<<64, 256>>>(P);
    k_node<<<NN, 256>>>(x, P);
    k_p1a<<<592, 256>>>(x, ei, wig);
    k_p1b<<<592, 256>>>(zn, dist, ei, wig, P, out);
}

// round 7
// speedup vs baseline: 1.3916x; 1.3916x over previous
#include <cuda_runtime.h>
#include <math.h>

#define NN 4000
#define NE 60000

// ---------------- scratch ----------------
__device__ float g_WA[2][4096];   // Ws@Wa per set
__device__ float g_WTA[2][4096];  // Wt@Wa per set
__device__ float g_WeA[2][2048];  // We@Wa per set
__device__ float g_Ut[2][512];    // [set][hd][h]  (Wv·Wo folded)
__device__ float g_G[2][256];     // [set][hd][ce] = Ut @ We^T
__device__ float g_A[NN * 3072];  // [n][part][16][64]; part 0=As set0,1=As set1,2=At own
__device__ float g_Y3[NN * 576];  // [n][part][3][64]; part 0=Ys set0,1=Ys set1,2=Yt own
__device__ float g_eexp[NE * 8];  // exp(logit)
__device__ float g_expsum[NN * 8];
__device__ int   g_mask[NN];

struct ParSet {
    const float *emb_s, *emb_t, *w_d, *We, *Ws, *Wt, *Wa, *va, *Wv, *Wo;
};
struct Par2 { ParSet s[2]; };

// ---------------- mask dtype sniff (bool/int32/float32) ----------------
__global__ void k_mask(const void* nm) {
    __shared__ int s_max, s_s1;
    if (threadIdx.x == 0) { s_max = 0; s_s1 = 0; }
    __syncthreads();
    const unsigned char* bp = (const unsigned char*)nm;
    int lm = 0, ls = 0;
    for (int i = threadIdx.x; i < NN; i += blockDim.x) {
        int v = bp[i];
        if (v > lm) lm = v;
        if ((i & 3) == 1) ls += v;
    }
    atomicMax(&s_max, lm);
    atomicAdd(&s_s1, ls);
    __syncthreads();
    int mode = (s_max > 1) ? 2 : (s_s1 > 0 ? 0 : 1);
    for (int n = threadIdx.x; n < NN; n += blockDim.x) {
        int v;
        if (mode == 0)      v = (bp[n] != 0);
        else if (mode == 1) v = (((const int*)nm)[n] != 0);
        else                v = (((const float*)nm)[n] != 0.0f);
        g_mask[n] = v;
    }
}

// ---------------- weight folds + zeroing ----------------
__global__ void k_small(Par2 P, float* out) {
    int tid = blockIdx.x * blockDim.x + threadIdx.x;
    int stride = gridDim.x * blockDim.x;
    // WA / WTA: 4 mats x 64 x 64
    for (int i = tid; i < 16384; i += stride) {
        int mat = i >> 12, c = (i >> 6) & 63, j = i & 63;
        int set = mat & 1;
        const float* W  = (mat < 2) ? P.s[set].Ws : P.s[set].Wt;
        const float* Wa = P.s[set].Wa;
        float s = 0.0f;
        for (int h = 0; h < 64; h++) s += W[c * 64 + h] * Wa[h * 64 + j];
        if (mat < 2) g_WA[set][c * 64 + j] = s;
        else         g_WTA[set][c * 64 + j] = s;
    }
    // WeA: 2 x 32 x 64
    for (int i = tid; i < 4096; i += stride) {
        int set = i >> 11, ce = (i >> 6) & 31, j = i & 63;
        const float* We = P.s[set].We;
        const float* Wa = P.s[set].Wa;
        float s = 0.0f;
        for (int h = 0; h < 64; h++) s += We[ce * 64 + h] * Wa[h * 64 + j];
        g_WeA[set][ce * 64 + j] = s;
    }
    // Ut: [set][hd][h]
    for (int i = tid; i < 1024; i += stride) {
        int set = i >> 9, r = i & 511, hd = r >> 6, h = r & 63;
        const float* Wv = P.s[set].Wv;
        const float* Wo = P.s[set].Wo;
        float s = 0.0f;
        #pragma unroll
        for (int vc = 0; vc < 8; vc++)
            s += Wv[h * 64 + hd * 8 + vc] * Wo[hd * 8 + vc];
        g_Ut[set][hd * 64 + h] = s;
    }
    // G: [set][hd][ce] = sum_h Ut[hd][h] * We[ce][h]
    for (int i = tid; i < 512; i += stride) {
        int set = i >> 8, r = i & 255, hd = r >> 5, ce = r & 31;
        const float* Wv = P.s[set].Wv;
        const float* Wo = P.s[set].Wo;
        const float* We = P.s[set].We;
        float s = 0.0f;
        for (int h = 0; h < 64; h++) {
            float ut = 0.0f;
            #pragma unroll
            for (int vc = 0; vc < 8; vc++)
                ut += Wv[h * 64 + hd * 8 + vc] * Wo[hd * 8 + vc];
            s += ut * We[ce * 64 + h];
        }
        g_G[set][hd * 32 + ce] = s;
    }
    for (int i = tid; i < NN * 8; i += stride) g_expsum[i] = 0.0f;
    for (int i = tid; i < NN * 3; i += stride) out[i] = 0.0f;
}

// ---------------- per-node GEMM: A = X@(W@Wa) (3 parts), Y3 = X[1:4]@W ----------------
__global__ __launch_bounds__(256)
void k_node(const float* __restrict__ x, Par2 P) {
    __shared__ float Xs[64 * 20];           // [c][m] padded rows of 20
    int n = blockIdx.x;
    int tid = threadIdx.x;
    int bn = g_mask[n];

    for (int i = tid; i < 1024; i += 256) {
        int m = i >> 6, c = i & 63;
        Xs[c * 20 + m] = x[(size_t)n * 1024 + i];
    }
    __syncthreads();

    int mq = tid >> 6;          // 0..3
    int q  = tid & 63;
    int part = q >> 4;          // 0..3
    int h4 = (q & 15) * 4;

    if (part < 3) {
        const float* Wp = (part == 0) ? g_WA[0] : (part == 1) ? g_WA[1] : g_WTA[bn];
        float4 acc0 = {0,0,0,0}, acc1 = {0,0,0,0}, acc2 = {0,0,0,0}, acc3 = {0,0,0,0};
        #pragma unroll 8
        for (int k = 0; k < 64; k++) {
            float4 xa = *(const float4*)&Xs[k * 20 + mq * 4];
            float4 w  = __ldg((const float4*)(Wp + k * 64 + h4));
            acc0.x += xa.x * w.x; acc0.y += xa.x * w.y; acc0.z += xa.x * w.z; acc0.w += xa.x * w.w;
            acc1.x += xa.y * w.x; acc1.y += xa.y * w.y; acc1.z += xa.y * w.z; acc1.w += xa.y * w.w;
            acc2.x += xa.z * w.x; acc2.y += xa.z * w.y; acc2.z += xa.z * w.z; acc2.w += xa.z * w.w;
            acc3.x += xa.w * w.x; acc3.y += xa.w * w.y; acc3.z += xa.w * w.z; acc3.w += xa.w * w.w;
        }
        float* dst = g_A + (size_t)n * 3072 + part * 1024 + (mq * 4) * 64 + h4;
        *(float4*)(dst)       = acc0;
        *(float4*)(dst + 64)  = acc1;
        *(float4*)(dst + 128) = acc2;
        *(float4*)(dst + 192) = acc3;
    } else if (mq < 3) {
        // Y3: part = mq (0=Ys set0, 1=Ys set1, 2=Yt own); rows m=1..3 with raw Ws/Wt
        const float* Wr = (mq == 0) ? P.s[0].Ws : (mq == 1) ? P.s[1].Ws : P.s[bn].Wt;
        float4 acc0 = {0,0,0,0}, acc1 = {0,0,0,0}, acc2 = {0,0,0,0};
        #pragma unroll 8
        for (int k = 0; k < 64; k++) {
            float4 xa = *(const float4*)&Xs[k * 20];   // m0..m3; use y,z,w
            float4 w  = __ldg((const float4*)(Wr + k * 64 + h4));
            acc0.x += xa.y * w.x; acc0.y += xa.y * w.y; acc0.z += xa.y * w.z; acc0.w += xa.y * w.w;
            acc1.x += xa.z * w.x; acc1.y += xa.z * w.y; acc1.z += xa.z * w.z; acc1.w += xa.z * w.w;
            acc2.x += xa.w * w.x; acc2.y += xa.w * w.y; acc2.z += xa.w * w.z; acc2.w += xa.w * w.w;
        }
        float* dst = g_Y3 + (size_t)n * 576 + mq * 192 + h4;
        *(float4*)(dst)       = acc0;
        *(float4*)(dst + 64)  = acc1;
        *(float4*)(dst + 128) = acc2;
    }
}

// ---------------- pass 1: logits + exp-sum (flat, 2 edges/warp) ----------------
__global__ __launch_bounds__(256)
void k_pass1(const int* __restrict__ zn, const float* __restrict__ dist,
             const int* __restrict__ ei, const float* __restrict__ wig, Par2 P) {
    __shared__ float s_WeA[2 * 2048];     // 16KB
    int tid = threadIdx.x;
    {
        const float* srcp = &g_WeA[0][0];
        for (int i = tid * 4; i < 4096; i += 1024)
            *(float4*)(s_WeA + i) = __ldg((const float4*)(srcp + i));
    }
    __syncthreads();

    int l  = tid & 31;
    int wid = tid >> 5;
    int le = l >> 4;
    int q  = l & 15;
    int eg = blockIdx.x * 16 + wid * 2 + le;

    int src = ei[eg], dst = ei[NE + eg];
    int b = g_mask[dst];
    const ParSet& pp = P.s[b];

    float dq = __ldg(wig + (size_t)eg * 256 + q);

    int zs = zn[src], zt = zn[dst];
    float dd = dist[eg];
    float z0 = dd * __ldg(pp.w_d + q)      + __ldg(pp.emb_s + zs * 32 + q)      + __ldg(pp.emb_t + zt * 32 + q);
    float z1 = dd * __ldg(pp.w_d + q + 16) + __ldg(pp.emb_s + zs * 32 + q + 16) + __ldg(pp.emb_t + zt * 32 + q + 16);
    float ev0 = z0 / (1.0f + __expf(-z0));
    float ev1 = z1 / (1.0f + __expf(-z1));

    const float4* As = (const float4*)(g_A + (size_t)src * 3072 + b * 1024);
    const float4* At = (const float4*)(g_A + (size_t)dst * 3072 + 2 * 1024);

    float4 acc = {0,0,0,0};
    #pragma unroll
    for (int n = 0; n < 16; n++) {
        float dn = __shfl_sync(0xffffffffu, dq, (le << 4) | n);
        float4 a1 = __ldg(As + n * 16 + q);
        float4 a2 = __ldg(At + n * 16 + q);
        acc.x += dn * (a1.x + a2.x);
        acc.y += dn * (a1.y + a2.y);
        acc.z += dn * (a1.z + a2.z);
        acc.w += dn * (a1.w + a2.w);
    }
    const float* sW = s_WeA + b * 2048;
    #pragma unroll 8
    for (int ce = 0; ce < 32; ce++) {
        float evv = __shfl_sync(0xffffffffu, (ce < 16) ? ev0 : ev1, (le << 4) | (ce & 15));
        float4 w = *(const float4*)(sW + ce * 64 + q * 4);
        acc.x += evv * w.x; acc.y += evv * w.y; acc.z += evv * w.z; acc.w += evv * w.w;
    }
    float4 vv = __ldg((const float4*)(pp.va + q * 4));
    float a0 = ((acc.x > 0.f) ? acc.x : 0.2f * acc.x) * vv.x;
    float a1 = ((acc.y > 0.f) ? acc.y : 0.2f * acc.y) * vv.y;
    float a2 = ((acc.z > 0.f) ? acc.z : 0.2f * acc.z) * vv.z;
    float a3 = ((acc.w > 0.f) ? acc.w : 0.2f * acc.w) * vv.w;
    float s = a0 + a1 + a2 + a3;
    s += __shfl_xor_sync(0xffffffffu, s, 1);
    if ((q & 1) == 0) {
        int head = q >> 1;
        float el = __expf(s);
        g_eexp[eg * 8 + head] = el;
        atomicAdd(&g_expsum[dst * 8 + head], el);
    }
}

// ---------------- pass 2: alpha, Ut/G-folded values, Y3 outputs (flat) ----------------
__global__ __launch_bounds__(256)
void k_pass2(const int* __restrict__ zn, const float* __restrict__ dist,
             const int* __restrict__ ei, const float* __restrict__ wig,
             Par2 P, float* __restrict__ out) {
    __shared__ float sUt[1024];     // 4KB  (both sets)
    __shared__ float sG[512];       // 2KB  (both sets)
    __shared__ float swd[64];
    int tid = threadIdx.x;
    for (int i = tid * 4; i < 1024; i += 1024)
        *(float4*)(sUt + i) = __ldg((const float4*)(&g_Ut[0][0] + i));
    for (int i = tid; i < 512; i += 256)
        sG[i] = (&g_G[0][0])[i];
    if (tid < 32) swd[tid] = __ldg(P.s[0].w_d + tid);
    if (tid >= 32 && tid < 64) swd[tid] = __ldg(P.s[1].w_d + tid - 32);
    __syncthreads();

    int l  = tid & 31;
    int wid = tid >> 5;
    int le = l >> 4;
    int q  = l & 15;
    int eg = blockIdx.x * 16 + wid * 2 + le;

    int src = ei[eg], dst = ei[NE + eg];
    int b = g_mask[dst];
    const ParSet& pp = P.s[b];

    // alpha on lanes q<8
    float al = 0.0f;
    if (q < 8)
        al = g_eexp[eg * 8 + q] / (g_expsum[dst * 8 + q] + 1e-9f);

    // p[4q..] = sum_hd Ut[b][hd][4q..]*alpha[hd]; pinj weights via G
    float4 p = {0, 0, 0, 0};
    float w0 = 0.0f, w1 = 0.0f;
    #pragma unroll
    for (int hd = 0; hd < 8; hd++) {
        float av = __shfl_sync(0xffffffffu, al, (le << 4) | hd);
        float4 u = *(const float4*)(sUt + b * 512 + hd * 64 + q * 4);
        p.x += av * u.x; p.y += av * u.y; p.z += av * u.z; p.w += av * u.w;
        w0 += av * sG[b * 256 + hd * 32 + q];
        w1 += av * sG[b * 256 + hd * 32 + q + 16];
    }

    // edge scalars
    int zs = zn[src], zt = zn[dst];
    float dd = __ldg(dist + eg);
    float z0 = dd * swd[b * 32 + q]      + __ldg(pp.emb_s + zs * 32 + q)      + __ldg(pp.emb_t + zt * 32 + q);
    float z1 = dd * swd[b * 32 + q + 16] + __ldg(pp.emb_s + zs * 32 + q + 16) + __ldg(pp.emb_t + zt * 32 + q + 16);
    float ev0 = z0 / (1.0f + __expf(-z0));
    float ev1 = z1 / (1.0f + __expf(-z1));
    float pinj = ev0 * w0 + ev1 * w1;

    // output rows via Y3
    const float4* Ys = (const float4*)(g_Y3 + (size_t)src * 576 + b * 192);
    const float4* Yt = (const float4*)(g_Y3 + (size_t)dst * 576 + 384);
    float o0, o1, o2;
    {
        float4 y, t;
        y = __ldg(Ys + q);       t = __ldg(Yt + q);
        o0 = p.x*(y.x+t.x) + p.y*(y.y+t.y) + p.z*(y.z+t.z) + p.w*(y.w+t.w);
        y = __ldg(Ys + 16 + q);  t = __ldg(Yt + 16 + q);
        o1 = p.x*(y.x+t.x) + p.y*(y.y+t.y) + p.z*(y.z+t.z) + p.w*(y.w+t.w);
        y = __ldg(Ys + 32 + q);  t = __ldg(Yt + 32 + q);
        o2 = p.x*(y.x+t.x) + p.y*(y.y+t.y) + p.z*(y.z+t.z) + p.w*(y.w+t.w);
    }

    // reduce 4 scalars over 16-lane group
    #pragma unroll
    for (int off = 8; off; off >>= 1) {
        o0   += __shfl_down_sync(0xffffffffu, o0, off, 16);
        o1   += __shfl_down_sync(0xffffffffu, o1, off, 16);
        o2   += __shfl_down_sync(0xffffffffu, o2, off, 16);
        pinj += __shfl_down_sync(0xffffffffu, pinj, off, 16);
    }
    if (q == 0) {
        float d1 = __ldg(wig + (size_t)eg * 256 + 1);
        float d2 = __ldg(wig + (size_t)eg * 256 + 2);
        float d3 = __ldg(wig + (size_t)eg * 256 + 3);
        atomicAdd(&out[dst * 3 + 0], o0 + pinj * d1);
        atomicAdd(&out[dst * 3 + 1], o1 + pinj * d2);
        atomicAdd(&out[dst * 3 + 2], o2 + pinj * d3);
    }
}

extern "C" void kernel_launch(void* const* d_in, const int* in_sizes, int n_in,
                              void* d_out, int out_size) {
    const float* x    = (const float*)d_in[0];
    const int*   zn   = (const int*)d_in[1];
    const float* dist = (const float*)d_in[2];
    const int*   ei   = (const int*)d_in[3];
    const void*  nm   = d_in[4];
    const float* wig  = (const float*)d_in[5];

    Par2 P;
    for (int s = 0; s < 2; s++) {
        int base = 6 + s * 10;
        P.s[s].emb_s = (const float*)d_in[base + 0];
        P.s[s].emb_t = (const float*)d_in[base + 1];
        P.s[s].w_d   = (const float*)d_in[base + 2];
        P.s[s].We    = (const float*)d_in[base + 3];
        P.s[s].Ws    = (const float*)d_in[base + 4];
        P.s[s].Wt    = (const float*)d_in[base + 5];
        P.s[s].Wa    = (const float*)d_in[base + 6];
        P.s[s].va    = (const float*)d_in[base + 7];
        P.s[s].Wv    = (const float*)d_in[base + 8];
        P.s[s].Wo    = (const float*)d_in[base + 9];
    }
    float* out = (float*)d_out;

    k_mask<<<1, 1024>>>(nm);
    k_small<<<64, 256>>>(P, out);
    k_node<<<NN, 256>>>(x, P);
    k_pass1<<<NE / 16, 256>>>(zn, dist, ei, wig, P);
    k_pass2<<<NE / 16, 256>>>(zn, dist, ei, wig, P, out);
}

// round 8
// speedup vs baseline: 1.4286x; 1.0266x over previous
#include <cuda_runtime.h>
#include <math.h>

#define NN 4000
#define NE 60000

// ---------------- scratch ----------------
__device__ float g_WA[2][4096];   // Ws@Wa per set
__device__ float g_WTA[2][4096];  // Wt@Wa per set
__device__ float g_WeA[2][2048];  // We@Wa per set
__device__ float g_Ut[2][512];    // [set][hd][h]  (Wv·Wo folded)
__device__ float g_G[2][256];     // [set][hd][ce] = Ut @ We^T
__device__ float g_A[NN * 3072];  // [n][part][16][64]; part 0=As set0,1=As set1,2=At own
__device__ float g_Y3[NN * 576];  // [n][part][3][64]; part 0=Ys set0,1=Ys set1,2=Yt own
__device__ float g_eexp[NE * 8];  // exp(logit)
__device__ float g_expsum[NN * 8];
__device__ int   g_mask[NN];

struct ParSet {
    const float *emb_s, *emb_t, *w_d, *We, *Ws, *Wt, *Wa, *va, *Wv, *Wo;
};
struct Par2 { ParSet s[2]; };

// ---------------- packed f32x2 helpers (FFMA2: 2x fp32 FMA throughput) ----------------
__device__ __forceinline__ unsigned long long pk2(float a) {
    unsigned long long r;
    asm("mov.b64 %0, {%1, %1};" : "=l"(r) : "r"(__float_as_uint(a)));
    return r;
}
__device__ __forceinline__ unsigned long long fma2(unsigned long long a,
                                                   unsigned long long b,
                                                   unsigned long long c) {
    unsigned long long d;
    asm("fma.rn.f32x2 %0, %1, %2, %3;" : "=l"(d) : "l"(a), "l"(b), "l"(c));
    return d;
}

// ---------------- weight folds + zeroing + mask sniff (block 64) ----------------
__global__ void k_small(Par2 P, const void* nm, float* out) {
    if (blockIdx.x == 64) {
        // mask dtype sniff (bool/int32/float32), 256 threads
        __shared__ int s_max, s_s1;
        if (threadIdx.x == 0) { s_max = 0; s_s1 = 0; }
        __syncthreads();
        const unsigned char* bp = (const unsigned char*)nm;
        int lm = 0, ls = 0;
        for (int i = threadIdx.x; i < NN; i += 256) {
            int v = bp[i];
            if (v > lm) lm = v;
            if ((i & 3) == 1) ls += v;
        }
        atomicMax(&s_max, lm);
        atomicAdd(&s_s1, ls);
        __syncthreads();
        int mode = (s_max > 1) ? 2 : (s_s1 > 0 ? 0 : 1);
        for (int n = threadIdx.x; n < NN; n += 256) {
            int v;
            if (mode == 0)      v = (bp[n] != 0);
            else if (mode == 1) v = (((const int*)nm)[n] != 0);
            else                v = (((const float*)nm)[n] != 0.0f);
            g_mask[n] = v;
        }
        return;
    }
    int tid = blockIdx.x * blockDim.x + threadIdx.x;
    const int stride = 64 * 256;
    // WA / WTA: 4 mats x 64 x 64
    for (int i = tid; i < 16384; i += stride) {
        int mat = i >> 12, c = (i >> 6) & 63, j = i & 63;
        int set = mat & 1;
        const float* W  = (mat < 2) ? P.s[set].Ws : P.s[set].Wt;
        const float* Wa = P.s[set].Wa;
        float s = 0.0f;
        for (int h = 0; h < 64; h++) s += W[c * 64 + h] * Wa[h * 64 + j];
        if (mat < 2) g_WA[set][c * 64 + j] = s;
        else         g_WTA[set][c * 64 + j] = s;
    }
    // WeA: 2 x 32 x 64
    for (int i = tid; i < 4096; i += stride) {
        int set = i >> 11, ce = (i >> 6) & 31, j = i & 63;
        const float* We = P.s[set].We;
        const float* Wa = P.s[set].Wa;
        float s = 0.0f;
        for (int h = 0; h < 64; h++) s += We[ce * 64 + h] * Wa[h * 64 + j];
        g_WeA[set][ce * 64 + j] = s;
    }
    // Ut: [set][hd][h]
    for (int i = tid; i < 1024; i += stride) {
        int set = i >> 9, r = i & 511, hd = r >> 6, h = r & 63;
        const float* Wv = P.s[set].Wv;
        const float* Wo = P.s[set].Wo;
        float s = 0.0f;
        #pragma unroll
        for (int vc = 0; vc < 8; vc++)
            s += Wv[h * 64 + hd * 8 + vc] * Wo[hd * 8 + vc];
        g_Ut[set][hd * 64 + h] = s;
    }
    // G: [set][hd][ce] = sum_h Ut[hd][h] * We[ce][h]
    for (int i = tid; i < 512; i += stride) {
        int set = i >> 8, r = i & 255, hd = r >> 5, ce = r & 31;
        const float* Wv = P.s[set].Wv;
        const float* Wo = P.s[set].Wo;
        const float* We = P.s[set].We;
        float s = 0.0f;
        for (int h = 0; h < 64; h++) {
            float ut = 0.0f;
            #pragma unroll
            for (int vc = 0; vc < 8; vc++)
                ut += Wv[h * 64 + hd * 8 + vc] * Wo[hd * 8 + vc];
            s += ut * We[ce * 64 + h];
        }
        g_G[set][hd * 32 + ce] = s;
    }
    for (int i = tid; i < NN * 8; i += stride) g_expsum[i] = 0.0f;
    for (int i = tid; i < NN * 3; i += stride) out[i] = 0.0f;
}

// ---------------- per-node GEMM: A = X@(W@Wa) (3 parts), Y3 = X[1:4]@W ----------------
__global__ __launch_bounds__(256)
void k_node(const float* __restrict__ x, Par2 P) {
    __shared__ float Xs[64 * 20];           // [c][m] padded rows of 20
    int n = blockIdx.x;
    int tid = threadIdx.x;
    int bn = g_mask[n];

    for (int i = tid; i < 1024; i += 256) {
        int m = i >> 6, c = i & 63;
        Xs[c * 20 + m] = x[(size_t)n * 1024 + i];
    }
    __syncthreads();

    int mq = tid >> 6;          // 0..3
    int q  = tid & 63;
    int part = q >> 4;          // 0..3
    int h4 = (q & 15) * 4;

    if (part < 3) {
        const float* Wp = (part == 0) ? g_WA[0] : (part == 1) ? g_WA[1] : g_WTA[bn];
        unsigned long long a0l = 0, a0h = 0, a1l = 0, a1h = 0,
                           a2l = 0, a2h = 0, a3l = 0, a3h = 0;
        #pragma unroll 8
        for (int k = 0; k < 64; k++) {
            float4 xa = *(const float4*)&Xs[k * 20 + mq * 4];
            double2 wd = __ldg((const double2*)(Wp + k * 64 + h4));
            unsigned long long w01 = __double_as_longlong(wd.x);
            unsigned long long w23 = __double_as_longlong(wd.y);
            unsigned long long xx;
            xx = pk2(xa.x); a0l = fma2(xx, w01, a0l); a0h = fma2(xx, w23, a0h);
            xx = pk2(xa.y); a1l = fma2(xx, w01, a1l); a1h = fma2(xx, w23, a1h);
            xx = pk2(xa.z); a2l = fma2(xx, w01, a2l); a2h = fma2(xx, w23, a2h);
            xx = pk2(xa.w); a3l = fma2(xx, w01, a3l); a3h = fma2(xx, w23, a3h);
        }
        double* dst = (double*)(g_A + (size_t)n * 3072 + part * 1024 + (mq * 4) * 64 + h4);
        dst[0] = __longlong_as_double(a0l); dst[1] = __longlong_as_double(a0h);
        dst += 32;
        dst[0] = __longlong_as_double(a1l); dst[1] = __longlong_as_double(a1h);
        dst += 32;
        dst[0] = __longlong_as_double(a2l); dst[1] = __longlong_as_double(a2h);
        dst += 32;
        dst[0] = __longlong_as_double(a3l); dst[1] = __longlong_as_double(a3h);
    } else if (mq < 3) {
        // Y3: part = mq (0=Ys set0, 1=Ys set1, 2=Yt own); rows m=1..3 with raw Ws/Wt
        const float* Wr = (mq == 0) ? P.s[0].Ws : (mq == 1) ? P.s[1].Ws : P.s[bn].Wt;
        unsigned long long a0l = 0, a0h = 0, a1l = 0, a1h = 0, a2l = 0, a2h = 0;
        #pragma unroll 8
        for (int k = 0; k < 64; k++) {
            float4 xa = *(const float4*)&Xs[k * 20];   // m0..m3; use y,z,w
            double2 wd = __ldg((const double2*)(Wr + k * 64 + h4));
            unsigned long long w01 = __double_as_longlong(wd.x);
            unsigned long long w23 = __double_as_longlong(wd.y);
            unsigned long long xx;
            xx = pk2(xa.y); a0l = fma2(xx, w01, a0l); a0h = fma2(xx, w23, a0h);
            xx = pk2(xa.z); a1l = fma2(xx, w01, a1l); a1h = fma2(xx, w23, a1h);
            xx = pk2(xa.w); a2l = fma2(xx, w01, a2l); a2h = fma2(xx, w23, a2h);
        }
        double* dst = (double*)(g_Y3 + (size_t)n * 576 + mq * 192 + h4);
        dst[0] = __longlong_as_double(a0l); dst[1] = __longlong_as_double(a0h);
        dst += 32;
        dst[0] = __longlong_as_double(a1l); dst[1] = __longlong_as_double(a1h);
        dst += 32;
        dst[0] = __longlong_as_double(a2l); dst[1] = __longlong_as_double(a2h);
    }
}

// ---------------- pass 1: logits + exp-sum (flat, 2 edges/warp) ----------------
__global__ __launch_bounds__(256)
void k_pass1(const int* __restrict__ zn, const float* __restrict__ dist,
             const int* __restrict__ ei, const float* __restrict__ wig, Par2 P) {
    __shared__ float s_WeA[2 * 2048];     // 16KB
    int tid = threadIdx.x;
    {
        const float* srcp = &g_WeA[0][0];
        for (int i = tid * 4; i < 4096; i += 1024)
            *(float4*)(s_WeA + i) = __ldg((const float4*)(srcp + i));
    }
    __syncthreads();

    int l  = tid & 31;
    int wid = tid >> 5;
    int le = l >> 4;
    int q  = l & 15;
    int eg = blockIdx.x * 16 + wid * 2 + le;

    int src = ei[eg], dst = ei[NE + eg];
    int b = g_mask[dst];
    const ParSet& pp = P.s[b];

    float dq = __ldg(wig + (size_t)eg * 256 + q);

    int zs = zn[src], zt = zn[dst];
    float dd = dist[eg];
    float z0 = dd * __ldg(pp.w_d + q)      + __ldg(pp.emb_s + zs * 32 + q)      + __ldg(pp.emb_t + zt * 32 + q);
    float z1 = dd * __ldg(pp.w_d + q + 16) + __ldg(pp.emb_s + zs * 32 + q + 16) + __ldg(pp.emb_t + zt * 32 + q + 16);
    float ev0 = z0 / (1.0f + __expf(-z0));
    float ev1 = z1 / (1.0f + __expf(-z1));

    const float4* As = (const float4*)(g_A + (size_t)src * 3072 + b * 1024);
    const float4* At = (const float4*)(g_A + (size_t)dst * 3072 + 2 * 1024);

    float4 acc = {0,0,0,0};
    #pragma unroll
    for (int n = 0; n < 16; n++) {
        float dn = __shfl_sync(0xffffffffu, dq, (le << 4) | n);
        float4 a1 = __ldg(As + n * 16 + q);
        float4 a2 = __ldg(At + n * 16 + q);
        acc.x += dn * (a1.x + a2.x);
        acc.y += dn * (a1.y + a2.y);
        acc.z += dn * (a1.z + a2.z);
        acc.w += dn * (a1.w + a2.w);
    }
    const float* sW = s_WeA + b * 2048;
    #pragma unroll 8
    for (int ce = 0; ce < 32; ce++) {
        float evv = __shfl_sync(0xffffffffu, (ce < 16) ? ev0 : ev1, (le << 4) | (ce & 15));
        float4 w = *(const float4*)(sW + ce * 64 + q * 4);
        acc.x += evv * w.x; acc.y += evv * w.y; acc.z += evv * w.z; acc.w += evv * w.w;
    }
    float4 vv = __ldg((const float4*)(pp.va + q * 4));
    float a0 = ((acc.x > 0.f) ? acc.x : 0.2f * acc.x) * vv.x;
    float a1 = ((acc.y > 0.f) ? acc.y : 0.2f * acc.y) * vv.y;
    float a2 = ((acc.z > 0.f) ? acc.z : 0.2f * acc.z) * vv.z;
    float a3 = ((acc.w > 0.f) ? acc.w : 0.2f * acc.w) * vv.w;
    float s = a0 + a1 + a2 + a3;
    s += __shfl_xor_sync(0xffffffffu, s, 1);
    if ((q & 1) == 0) {
        int head = q >> 1;
        float el = __expf(s);
        g_eexp[eg * 8 + head] = el;
        atomicAdd(&g_expsum[dst * 8 + head], el);
    }
}

// ---------------- pass 2: alpha, Ut/G-folded values, Y3 outputs (flat) ----------------
__global__ __launch_bounds__(256)
void k_pass2(const int* __restrict__ zn, const float* __restrict__ dist,
             const int* __restrict__ ei, const float* __restrict__ wig,
             Par2 P, float* __restrict__ out) {
    __shared__ float sUt[1024];     // 4KB  (both sets)
    __shared__ float sG[512];       // 2KB  (both sets)
    __shared__ float swd[64];
    int tid = threadIdx.x;
    for (int i = tid * 4; i < 1024; i += 1024)
        *(float4*)(sUt + i) = __ldg((const float4*)(&g_Ut[0][0] + i));
    for (int i = tid; i < 512; i += 256)
        sG[i] = (&g_G[0][0])[i];
    if (tid < 32) swd[tid] = __ldg(P.s[0].w_d + tid);
    if (tid >= 32 && tid < 64) swd[tid] = __ldg(P.s[1].w_d + tid - 32);
    __syncthreads();

    int l  = tid & 31;
    int wid = tid >> 5;
    int le = l >> 4;
    int q  = l & 15;
    int eg = blockIdx.x * 16 + wid * 2 + le;

    int src = ei[eg], dst = ei[NE + eg];
    int b = g_mask[dst];
    const ParSet& pp = P.s[b];

    // alpha on lanes q<8
    float al = 0.0f;
    if (q < 8)
        al = g_eexp[eg * 8 + q] / (g_expsum[dst * 8 + q] + 1e-9f);

    // p[4q..] = sum_hd Ut[b][hd][4q..]*alpha[hd]; pinj weights via G
    float4 p = {0, 0, 0, 0};
    float w0 = 0.0f, w1 = 0.0f;
    #pragma unroll
    for (int hd = 0; hd < 8; hd++) {
        float av = __shfl_sync(0xffffffffu, al, (le << 4) | hd);
        float4 u = *(const float4*)(sUt + b * 512 + hd * 64 + q * 4);
        p.x += av * u.x; p.y += av * u.y; p.z += av * u.z; p.w += av * u.w;
        w0 += av * sG[b * 256 + hd * 32 + q];
        w1 += av * sG[b * 256 + hd * 32 + q + 16];
    }

    // edge scalars
    int zs = zn[src], zt = zn[dst];
    float dd = __ldg(dist + eg);
    float z0 = dd * swd[b * 32 + q]      + __ldg(pp.emb_s + zs * 32 + q)      + __ldg(pp.emb_t + zt * 32 + q);
    float z1 = dd * swd[b * 32 + q + 16] + __ldg(pp.emb_s + zs * 32 + q + 16) + __ldg(pp.emb_t + zt * 32 + q + 16);
    float ev0 = z0 / (1.0f + __expf(-z0));
    float ev1 = z1 / (1.0f + __expf(-z1));
    float pinj = ev0 * w0 + ev1 * w1;

    // output rows via Y3
    const float4* Ys = (const float4*)(g_Y3 + (size_t)src * 576 + b * 192);
    const float4* Yt = (const float4*)(g_Y3 + (size_t)dst * 576 + 384);
    float o0, o1, o2;
    {
        float4 y, t;
        y = __ldg(Ys + q);       t = __ldg(Yt + q);
        o0 = p.x*(y.x+t.x) + p.y*(y.y+t.y) + p.z*(y.z+t.z) + p.w*(y.w+t.w);
        y = __ldg(Ys + 16 + q);  t = __ldg(Yt + 16 + q);
        o1 = p.x*(y.x+t.x) + p.y*(y.y+t.y) + p.z*(y.z+t.z) + p.w*(y.w+t.w);
        y = __ldg(Ys + 32 + q);  t = __ldg(Yt + 32 + q);
        o2 = p.x*(y.x+t.x) + p.y*(y.y+t.y) + p.z*(y.z+t.z) + p.w*(y.w+t.w);
    }

    // reduce 4 scalars over 16-lane group
    #pragma unroll
    for (int off = 8; off; off >>= 1) {
        o0   += __shfl_down_sync(0xffffffffu, o0, off, 16);
        o1   += __shfl_down_sync(0xffffffffu, o1, off, 16);
        o2   += __shfl_down_sync(0xffffffffu, o2, off, 16);
        pinj += __shfl_down_sync(0xffffffffu, pinj, off, 16);
    }
    if (q == 0) {
        float d1 = __ldg(wig + (size_t)eg * 256 + 1);
        float d2 = __ldg(wig + (size_t)eg * 256 + 2);
        float d3 = __ldg(wig + (size_t)eg * 256 + 3);
        atomicAdd(&out[dst * 3 + 0], o0 + pinj * d1);
        atomicAdd(&out[dst * 3 + 1], o1 + pinj * d2);
        atomicAdd(&out[dst * 3 + 2], o2 + pinj * d3);
    }
}

extern "C" void kernel_launch(void* const* d_in, const int* in_sizes, int n_in,
                              void* d_out, int out_size) {
    const float* x    = (const float*)d_in[0];
    const int*   zn   = (const int*)d_in[1];
    const float* dist = (const float*)d_in[2];
    const int*   ei   = (const int*)d_in[3];
    const void*  nm   = d_in[4];
    const float* wig  = (const float*)d_in[5];

    Par2 P;
    for (int s = 0; s < 2; s++) {
        int base = 6 + s * 10;
        P.s[s].emb_s = (const float*)d_in[base + 0];
        P.s[s].emb_t = (const float*)d_in[base + 1];
        P.s[s].w_d   = (const float*)d_in[base + 2];
        P.s[s].We    = (const float*)d_in[base + 3];
        P.s[s].Ws    = (const float*)d_in[base + 4];
        P.s[s].Wt    = (const float*)d_in[base + 5];
        P.s[s].Wa    = (const float*)d_in[base + 6];
        P.s[s].va    = (const float*)d_in[base + 7];
        P.s[s].Wv    = (const float*)d_in[base + 8];
        P.s[s].Wo    = (const float*)d_in[base + 9];
    }
    float* out = (float*)d_out;

    k_small<<<65, 256>>>(P, nm, out);
    k_node<<<NN, 256>>>(x, P);
    k_pass1<<<NE / 16, 256>>>(zn, dist, ei, wig, P);
    k_pass2<<<NE / 16, 256>>>(zn, dist, ei, wig, P, out);
}